// round 4
// baseline (speedup 1.0000x reference)
#include <cuda_runtime.h>
#include <cstddef>

#define B_      128
#define NNZ_    128
#define H_      128
#define KOUT_   4096
#define FDIM_   135909

#define L1B_PER_B  16                      // layer1 blocks per batch row
#define L1_BLOCKS  (B_ * L1B_PER_B)        // 2048
#define L2B_PER_B  128                     // layer2 blocks per batch row
#define L2_BLOCKS  (B_ * L2B_PER_B)        // 16384

// Device-global scratch (no allocations allowed).
__device__ float g_val1[B_ * H_];
__device__ int   g_cnt1[B_];               // layer1 completion per b (zero-init)
__device__ int   g_cnt2[B_];               // layer2 completion per b (for self-reset)

// ---------------------------------------------------------------------------
// Fused kernel.
//   bid <  L1_BLOCKS : layer1  — val1[b,h] = relu(sum_i v[b,i]*W1[h,f[b,i]] + b1[h])
//                      8 warps = 8 h per block, warp-reduce, 16 blocks per b.
//                      Random 32B-sector gathers (sector-efficiency bound).
//   bid >= L1_BLOCKS : layer2  — val2[b,k] = <val1[b],W2[lab[b,k]]> + b2[lab]
//                      R1 config: warp=4 outputs (4 coalesced float4 row loads
//                      in flight), 8 warps = 32 outputs per block.
//                      Streaming 512B-row gathers (bandwidth bound).
// Layer2 block for b spin-waits on cnt1[b]==16, so layer2 of early rows runs
// concurrently with layer1 of late rows — mixing the two traffic classes to
// fill DRAM. Counters self-reset so graph replays behave identically.
// ---------------------------------------------------------------------------
__global__ __launch_bounds__(256) void fused_kernel(
    const float* __restrict__ inv,
    const int*   __restrict__ fidx,
    const float* __restrict__ W1,
    const float* __restrict__ b1,
    const int*   __restrict__ lab,
    const float* __restrict__ W2,
    const float* __restrict__ b2,
    float*       __restrict__ out,
    float*       __restrict__ out_lab)   // may be null
{
    const int tid  = threadIdx.x;
    const int warp = tid >> 5;
    const int lane = tid & 31;

    if (blockIdx.x < L1_BLOCKS) {
        // ------------------------------ layer 1 ------------------------------
        const int b = blockIdx.x >> 4;
        const int h = ((blockIdx.x & 15) << 3) + warp;

        __shared__ int   sidx[NNZ_];
        __shared__ float sval[NNZ_];
        if (tid < 128) sidx[tid]       = fidx[(b << 7) + tid];
        else           sval[tid - 128] = inv [(b << 7) + tid - 128];
        __syncthreads();

        const float* w = W1 + (size_t)h * FDIM_;
        const int4   i4 = reinterpret_cast<const int4*>(sidx)[lane];
        const float4 v4 = reinterpret_cast<const float4*>(sval)[lane];

        float acc = __ldg(w + i4.x) * v4.x + __ldg(w + i4.y) * v4.y +
                    __ldg(w + i4.z) * v4.z + __ldg(w + i4.w) * v4.w;

        #pragma unroll
        for (int o = 16; o > 0; o >>= 1)
            acc += __shfl_xor_sync(0xffffffffu, acc, o);

        if (lane == 0)
            g_val1[(b << 7) + h] = fmaxf(acc + __ldg(b1 + h), 0.0f);

        __syncthreads();
        __threadfence();                       // publish val1 before counting
        if (tid == 0) atomicAdd(&g_cnt1[b], 1);
        return;
    }

    // -------------------------------- layer 2 --------------------------------
    const int bid2  = blockIdx.x - L1_BLOCKS;
    const int b     = bid2 >> 7;                      // 128 blocks per b
    const int kbase = ((bid2 & 127) << 5) + (warp << 2);

    if (tid == 0) {
        while (atomicAdd(&g_cnt1[b], 0) < L1B_PER_B) __nanosleep(64);
        __threadfence();                      // acquire val1
    }
    __syncthreads();

    __shared__ float4 s4[32];
    if (tid < 32)
        s4[tid] = reinterpret_cast<const float4*>(g_val1 + (b << 7))[tid];
    __syncthreads();

    const float4 sv   = s4[lane];
    const int    base = (b << 12) + kbase;

    int rows[4];
    #pragma unroll
    for (int j = 0; j < 4; j++) rows[j] = lab[base + j];

    float acc[4];
    #pragma unroll
    for (int j = 0; j < 4; j++) {
        const float4 wv = __ldg(reinterpret_cast<const float4*>(W2) +
                                ((size_t)rows[j] << 5) + lane);
        acc[j] = wv.x * sv.x + wv.y * sv.y + wv.z * sv.z + wv.w * sv.w;
    }

    #pragma unroll
    for (int j = 0; j < 4; j++) {
        #pragma unroll
        for (int o = 16; o > 0; o >>= 1)
            acc[j] += __shfl_xor_sync(0xffffffffu, acc[j], o);
    }

    if (lane < 4) {
        const int j = lane;
        const int r = rows[j];
        out[base + j] = acc[j] + __ldg(b2 + r);
        if (out_lab) out_lab[base + j] = (float)r;
    }

    // self-reset counters so every graph replay starts clean
    __syncthreads();
    if (tid == 0) {
        const int d = atomicAdd(&g_cnt2[b], 1);
        if (d == L2B_PER_B - 1) {
            g_cnt1[b] = 0;
            g_cnt2[b] = 0;
            __threadfence();
        }
    }
}

// ---------------------------------------------------------------------------
extern "C" void kernel_launch(void* const* d_in, const int* in_sizes, int n_in,
                              void* d_out, int out_size)
{
    const float* inv  = (const float*)d_in[0];   // in_values        [B, NNZ]
    const int*   fidx = (const int*)  d_in[1];   // active_in_indices[B, NNZ]
    const int*   lab  = (const int*)  d_in[2];   // active_label_idx [B, KOUT]
    const float* W1   = (const float*)d_in[3];   // [H, FDIM]
    const float* b1   = (const float*)d_in[4];   // [H]
    const float* W2   = (const float*)d_in[5];   // [C, H]
    const float* b2   = (const float*)d_in[6];   // [C]

    float* out = (float*)d_out;
    const int n_val2 = B_ * KOUT_;
    float* out_lab = (out_size >= 2 * n_val2) ? (out + n_val2) : nullptr;

    fused_kernel<<<L1_BLOCKS + L2_BLOCKS, 256>>>(inv, fidx, W1, b1,
                                                 lab, W2, b2, out, out_lab);
}